// round 5
// baseline (speedup 1.0000x reference)
#include <cuda_runtime.h>

// Temporal cosine regularizer, single fused kernel (R5).
//   out = -0.02/(N-1) * sum_i <x_i,x_{i+1}> / (max(||x_i||,eps)*max(||x_{i+1}||,eps))
//
// HBM-bound, 512 MB read-once. cp.async 3-stage smem ring (in-flight bytes in
// SMEM, not registers -> occ stays 8 blocks/SM). R5 fixes two R4 leaks:
//  (1) prefetch predicated to the block's own rows (R4 wasted 16 MB = 3% reading
//      2 rows past each block's range); skipped iters commit EMPTY groups so
//      cp.async group counting stays uniform.
//  (2) wait_group 2 (not 1): the consumed row was committed 2 groups ago, so
//      2 newer groups may stay pending -> true 3-stage overlap.
// No __syncthreads in the pipeline: each thread reads back only the bytes it
// copied; the stage overwritten at iter k was consumed by the same thread at k-1.

#define COLS     2048
#define RPB      64
#define NTHREADS 256
#define STAGES   3

__device__ float        g_partials[8192];
__device__ unsigned int g_count = 0;

__device__ __forceinline__ void cp_async16(void* smem_dst, const void* gmem_src) {
    unsigned int s = (unsigned int)__cvta_generic_to_shared(smem_dst);
    asm volatile("cp.async.cg.shared.global [%0], [%1], 16;" :: "r"(s), "l"(gmem_src));
}

__device__ __forceinline__ float warp_reduce_f(float v) {
#pragma unroll
    for (int o = 16; o > 0; o >>= 1) v += __shfl_xor_sync(0xffffffffu, v, o);
    return v;
}

__global__ void __launch_bounds__(NTHREADS, 8)
pair_dot_fused_kernel(const float* __restrict__ x, int N, float* __restrict__ out) {
    __shared__ __align__(16) float buf[STAGES][COLS];   // 24 KB ring
    __shared__ __align__(16) float s_sq[RPB + 1][8];    // aliased by finalize
    __shared__ __align__(16) float s_dp[RPB + 1][8];
    __shared__ bool s_last;

    const int tid  = threadIdx.x;
    const int lane = tid & 31;
    const int warp = tid >> 5;
    const int r0   = blockIdx.x * RPB;
    const int rlast = (r0 + RPB < N) ? r0 + RPB : N - 1;  // last row this block needs

    const int c0 = tid * 4;               // float index of this thread's 1st float4
    const int c1 = (tid + NTHREADS) * 4;  // 2nd float4

    // ---- prologue: rows r0, r0+1 into stages 0,1 (always valid: r0+1 <= rlast) ----
#pragma unroll
    for (int p = 0; p < STAGES - 1; ++p) {
        const float* src = x + (size_t)(r0 + p) * COLS;
        cp_async16(&buf[p][c0], src + c0);
        cp_async16(&buf[p][c1], src + c1);
        asm volatile("cp.async.commit_group;");
    }

    float prev[8] = {0,0,0,0,0,0,0,0};

    // ---- pipelined mainloop over rows r0+k, k = 0..RPB ----
#pragma unroll 3
    for (int k = 0; k <= RPB; ++k) {
        // Prefetch row r0+k+2 ONLY if this block actually consumes it.
        // Otherwise commit an empty group (keeps group arithmetic uniform).
        {
            const int r = r0 + k + STAGES - 1;
            if (r <= rlast) {
                const float* src = x + (size_t)r * COLS;
                const int sw = (k + STAGES - 1) % STAGES;
                cp_async16(&buf[sw][c0], src + c0);
                cp_async16(&buf[sw][c1], src + c1);
            }
            asm volatile("cp.async.commit_group;");
        }
        // Row k's group was committed 2 groups ago -> 2 newer may stay pending.
        asm volatile("cp.async.wait_group 2;");

        const int s = k % STAGES;
        float4 a = *reinterpret_cast<const float4*>(&buf[s][c0]);
        float4 b = *reinterpret_cast<const float4*>(&buf[s][c1]);
        float cur[8] = {a.x, a.y, a.z, a.w, b.x, b.y, b.z, b.w};

        float sq = 0.0f, dp = 0.0f;
        if (r0 + k < N) {
#pragma unroll
            for (int j = 0; j < 8; ++j) {
                sq = fmaf(cur[j], cur[j], sq);
                dp = fmaf(cur[j], prev[j], dp);
            }
        }
        sq = warp_reduce_f(sq);
        dp = warp_reduce_f(dp);
        if (lane == 0) { s_sq[k][warp] = sq; s_dp[k][warp] = dp; }

#pragma unroll
        for (int j = 0; j < 8; ++j) prev[j] = cur[j];
    }
    __syncthreads();

    // ---- warp 0: per-row cosine terms, fp64 accumulate ----
    if (warp == 0) {
        double acc = 0.0;
        for (int rr = 1 + lane; rr <= RPB; rr += 32) {
            if (r0 + rr < N) {                 // dot index r0+rr-1 <= N-2
                float n2a = 0.0f, n2b = 0.0f, d8 = 0.0f;
#pragma unroll
                for (int w = 0; w < 8; ++w) {
                    n2a += s_sq[rr - 1][w];
                    n2b += s_sq[rr][w];
                    d8  += s_dp[rr][w];
                }
                float na = fmaxf(sqrtf(n2a), 1e-12f);
                float nb = fmaxf(sqrtf(n2b), 1e-12f);
                acc += (double)(d8 / (na * nb));
            }
        }
#pragma unroll
        for (int o = 16; o > 0; o >>= 1)
            acc += __shfl_xor_sync(0xffffffffu, acc, o);
        if (lane == 0) g_partials[blockIdx.x] = (float)acc;
    }

    // ---- last-block-done: deterministic final reduction ----
    __threadfence();
    if (tid == 0) {
        unsigned int prev_cnt = atomicAdd(&g_count, 1u);
        s_last = (prev_cnt == gridDim.x - 1);
    }
    __syncthreads();

    if (s_last) {
        double* sd = reinterpret_cast<double*>(&s_sq[0][0]);  // dead storage reuse
        const int nb = gridDim.x;
        double a = 0.0;
        for (int i = tid; i < nb; i += NTHREADS)
            a += (double)__ldcg(&g_partials[i]);
        sd[tid] = a;
        __syncthreads();
#pragma unroll
        for (int o = NTHREADS / 2; o > 0; o >>= 1) {
            if (tid < o) sd[tid] += sd[tid + o];
            __syncthreads();
        }
        if (tid == 0) {
            out[0] = (float)(-2.0 * 0.01 * sd[0] / (double)(N - 1));
            g_count = 0;  // reset for next graph replay
        }
    }
}

extern "C" void kernel_launch(void* const* d_in, const int* in_sizes, int n_in,
                              void* d_out, int out_size) {
    const float* x = (const float*)d_in[0];
    const int N = in_sizes[0] / COLS;            // 65536
    const int nblocks = (N - 1 + RPB - 1) / RPB; // 1024
    pair_dot_fused_kernel<<<nblocks, NTHREADS>>>(x, N, (float*)d_out);
}

// round 6
// speedup vs baseline: 1.0260x; 1.0260x over previous
#include <cuda_runtime.h>

// Temporal cosine regularizer, single fused kernel (R6).
//   out = -0.02/(N-1) * sum_i <x_i,x_{i+1}> / (max(||x_i||,eps)*max(||x_{i+1}||,eps))
//
// HBM-bound, 512 MB read-once. cp.async 3-stage smem ring, occ 8 blocks/SM.
// R4 (branch-free, clamp N-1): best BW 6250 GB/s but +16MB DRAM (far-row clamp).
// R5 (predicated prefetch):    bytes fixed but BW fell 6% (branch broke issue).
// R6: branch-free clamp to rlast (this block's own last row) -> overflow
// prefetches are L2 hits, zero extra DRAM, SASS issue schedule identical to R4.
// wait_group 2 = true 3-stage depth. No __syncthreads in pipeline: each thread
// reads only bytes it copied; overwritten stage was consumed by same thread.

#define COLS     2048
#define RPB      64
#define NTHREADS 256
#define STAGES   3

__device__ float        g_partials[8192];
__device__ unsigned int g_count = 0;

__device__ __forceinline__ void cp_async16(void* smem_dst, const void* gmem_src) {
    unsigned int s = (unsigned int)__cvta_generic_to_shared(smem_dst);
    asm volatile("cp.async.cg.shared.global [%0], [%1], 16;" :: "r"(s), "l"(gmem_src));
}

__device__ __forceinline__ float warp_reduce_f(float v) {
#pragma unroll
    for (int o = 16; o > 0; o >>= 1) v += __shfl_xor_sync(0xffffffffu, v, o);
    return v;
}

__global__ void __launch_bounds__(NTHREADS, 8)
pair_dot_fused_kernel(const float* __restrict__ x, int N, float* __restrict__ out) {
    __shared__ __align__(16) float buf[STAGES][COLS];   // 24 KB ring
    __shared__ __align__(16) float s_sq[RPB + 1][8];    // aliased by finalize
    __shared__ __align__(16) float s_dp[RPB + 1][8];
    __shared__ bool s_last;

    const int tid  = threadIdx.x;
    const int lane = tid & 31;
    const int warp = tid >> 5;
    const int r0   = blockIdx.x * RPB;
    const int rlast = (r0 + RPB < N) ? r0 + RPB : N - 1;  // last row this block reads

    const int c0 = tid * 4;               // float index of this thread's 1st float4
    const int c1 = (tid + NTHREADS) * 4;  // 2nd float4

    // ---- prologue: rows r0, r0+1 into stages 0,1 (always <= rlast) ----
#pragma unroll
    for (int p = 0; p < STAGES - 1; ++p) {
        const float* src = x + (size_t)(r0 + p) * COLS;
        cp_async16(&buf[p][c0], src + c0);
        cp_async16(&buf[p][c1], src + c1);
        asm volatile("cp.async.commit_group;");
    }

    float prev[8] = {0,0,0,0,0,0,0,0};

    // ---- pipelined mainloop over rows r0+k, k = 0..RPB ----
#pragma unroll 3
    for (int k = 0; k <= RPB; ++k) {
        // Branch-free prefetch of row r0+k+2, clamped to rlast (overflow iters
        // re-read this block's own last row -> L2 hit, no extra DRAM).
        {
            int r = r0 + k + STAGES - 1;
            if (r > rlast) r = rlast;           // uniform min, stays branch-free
            const float* src = x + (size_t)r * COLS;
            const int sw = (k + STAGES - 1) % STAGES;
            cp_async16(&buf[sw][c0], src + c0);
            cp_async16(&buf[sw][c1], src + c1);
            asm volatile("cp.async.commit_group;");
        }
        // Row k's group committed 2 groups ago -> allow 2 newer pending.
        asm volatile("cp.async.wait_group 2;");

        const int s = k % STAGES;
        float4 a = *reinterpret_cast<const float4*>(&buf[s][c0]);
        float4 b = *reinterpret_cast<const float4*>(&buf[s][c1]);
        float cur[8] = {a.x, a.y, a.z, a.w, b.x, b.y, b.z, b.w};

        float sq = 0.0f, dp = 0.0f;
        if (r0 + k < N) {
#pragma unroll
            for (int j = 0; j < 8; ++j) {
                sq = fmaf(cur[j], cur[j], sq);
                dp = fmaf(cur[j], prev[j], dp);
            }
        }
        sq = warp_reduce_f(sq);
        dp = warp_reduce_f(dp);
        if (lane == 0) { s_sq[k][warp] = sq; s_dp[k][warp] = dp; }

#pragma unroll
        for (int j = 0; j < 8; ++j) prev[j] = cur[j];
    }
    __syncthreads();

    // ---- warp 0: per-row cosine terms, fp64 accumulate ----
    if (warp == 0) {
        double acc = 0.0;
        for (int rr = 1 + lane; rr <= RPB; rr += 32) {
            if (r0 + rr < N) {                 // dot index r0+rr-1 <= N-2
                float n2a = 0.0f, n2b = 0.0f, d8 = 0.0f;
#pragma unroll
                for (int w = 0; w < 8; ++w) {
                    n2a += s_sq[rr - 1][w];
                    n2b += s_sq[rr][w];
                    d8  += s_dp[rr][w];
                }
                float na = fmaxf(sqrtf(n2a), 1e-12f);
                float nb = fmaxf(sqrtf(n2b), 1e-12f);
                acc += (double)(d8 / (na * nb));
            }
        }
#pragma unroll
        for (int o = 16; o > 0; o >>= 1)
            acc += __shfl_xor_sync(0xffffffffu, acc, o);
        if (lane == 0) g_partials[blockIdx.x] = (float)acc;
    }

    // ---- last-block-done: deterministic final reduction ----
    __threadfence();
    if (tid == 0) {
        unsigned int prev_cnt = atomicAdd(&g_count, 1u);
        s_last = (prev_cnt == gridDim.x - 1);
    }
    __syncthreads();

    if (s_last) {
        double* sd = reinterpret_cast<double*>(&s_sq[0][0]);  // dead storage reuse
        const int nb = gridDim.x;
        double a = 0.0;
        for (int i = tid; i < nb; i += NTHREADS)
            a += (double)__ldcg(&g_partials[i]);
        sd[tid] = a;
        __syncthreads();
#pragma unroll
        for (int o = NTHREADS / 2; o > 0; o >>= 1) {
            if (tid < o) sd[tid] += sd[tid + o];
            __syncthreads();
        }
        if (tid == 0) {
            out[0] = (float)(-2.0 * 0.01 * sd[0] / (double)(N - 1));
            g_count = 0;  // reset for next graph replay
        }
    }
}

extern "C" void kernel_launch(void* const* d_in, const int* in_sizes, int n_in,
                              void* d_out, int out_size) {
    const float* x = (const float*)d_in[0];
    const int N = in_sizes[0] / COLS;            // 65536
    const int nblocks = (N - 1 + RPB - 1) / RPB; // 1024
    pair_dot_fused_kernel<<<nblocks, NTHREADS>>>(x, N, (float*)d_out);
}

// round 7
// speedup vs baseline: 1.0373x; 1.0110x over previous
#include <cuda_runtime.h>

// Temporal cosine regularizer, single fused kernel (R7).
//   out = -0.02/(N-1) * sum_i <x_i,x_{i+1}> / (max(||x_i||,eps)*max(||x_{i+1}||,eps))
//
// HBM-bound, 512 MiB read-once (545 MB incl. 1.56% structural boundary overlap).
// cp.async 3-stage smem ring, occ 8 blocks/SM. 2x2 ablation across R4-R6:
//   wait_group 1 + branch-free issue  -> 6250 GB/s   (R4)
//   wait_group 2 (either issue shape) -> ~5800 GB/s  (R5, R6)
// => R7 = R4's schedule (wait_group 1, always-issue) + clamp overflow prefetch
//    to rlast (block's own last row: L2 hit, no DRAM bytes; R4's N-1 clamp
//    cost +16 MB). Only the clamp target differs from R4's SASS.

#define COLS     2048
#define RPB      64
#define NTHREADS 256
#define STAGES   3

__device__ float        g_partials[8192];
__device__ unsigned int g_count = 0;

__device__ __forceinline__ void cp_async16(void* smem_dst, const void* gmem_src) {
    unsigned int s = (unsigned int)__cvta_generic_to_shared(smem_dst);
    asm volatile("cp.async.cg.shared.global [%0], [%1], 16;" :: "r"(s), "l"(gmem_src));
}

__device__ __forceinline__ float warp_reduce_f(float v) {
#pragma unroll
    for (int o = 16; o > 0; o >>= 1) v += __shfl_xor_sync(0xffffffffu, v, o);
    return v;
}

__global__ void __launch_bounds__(NTHREADS, 8)
pair_dot_fused_kernel(const float* __restrict__ x, int N, float* __restrict__ out) {
    __shared__ __align__(16) float buf[STAGES][COLS];   // 24 KB ring
    __shared__ __align__(16) float s_sq[RPB + 1][8];    // aliased by finalize
    __shared__ __align__(16) float s_dp[RPB + 1][8];
    __shared__ bool s_last;

    const int tid  = threadIdx.x;
    const int lane = tid & 31;
    const int warp = tid >> 5;
    const int r0   = blockIdx.x * RPB;
    const int rlast = (r0 + RPB < N) ? r0 + RPB : N - 1;  // last row this block reads

    const int c0 = tid * 4;               // float index of this thread's 1st float4
    const int c1 = (tid + NTHREADS) * 4;  // 2nd float4

    // ---- prologue: rows r0, r0+1 into stages 0,1 (always <= rlast) ----
#pragma unroll
    for (int p = 0; p < STAGES - 1; ++p) {
        const float* src = x + (size_t)(r0 + p) * COLS;
        cp_async16(&buf[p][c0], src + c0);
        cp_async16(&buf[p][c1], src + c1);
        asm volatile("cp.async.commit_group;");
    }

    float prev[8] = {0,0,0,0,0,0,0,0};

    // ---- pipelined mainloop over rows r0+k, k = 0..RPB ----
#pragma unroll 3
    for (int k = 0; k <= RPB; ++k) {
        // Branch-free prefetch of row r0+k+2, clamped to rlast (overflow iters
        // re-read this block's own last row -> cache hit, no extra DRAM).
        {
            int r = r0 + k + STAGES - 1;
            if (r > rlast) r = rlast;           // uniform min, branch-free
            const float* src = x + (size_t)r * COLS;
            const int sw = (k + STAGES - 1) % STAGES;
            cp_async16(&buf[sw][c0], src + c0);
            cp_async16(&buf[sw][c1], src + c1);
            asm volatile("cp.async.commit_group;");
        }
        // wait_group 1: the empirically fastest depth (R4 ablation).
        asm volatile("cp.async.wait_group 1;");

        const int s = k % STAGES;
        float4 a = *reinterpret_cast<const float4*>(&buf[s][c0]);
        float4 b = *reinterpret_cast<const float4*>(&buf[s][c1]);
        float cur[8] = {a.x, a.y, a.z, a.w, b.x, b.y, b.z, b.w};

        float sq = 0.0f, dp = 0.0f;
        if (r0 + k < N) {
#pragma unroll
            for (int j = 0; j < 8; ++j) {
                sq = fmaf(cur[j], cur[j], sq);
                dp = fmaf(cur[j], prev[j], dp);
            }
        }
        sq = warp_reduce_f(sq);
        dp = warp_reduce_f(dp);
        if (lane == 0) { s_sq[k][warp] = sq; s_dp[k][warp] = dp; }

#pragma unroll
        for (int j = 0; j < 8; ++j) prev[j] = cur[j];
    }
    __syncthreads();

    // ---- warp 0: per-row cosine terms, fp64 accumulate ----
    if (warp == 0) {
        double acc = 0.0;
        for (int rr = 1 + lane; rr <= RPB; rr += 32) {
            if (r0 + rr < N) {                 // dot index r0+rr-1 <= N-2
                float n2a = 0.0f, n2b = 0.0f, d8 = 0.0f;
#pragma unroll
                for (int w = 0; w < 8; ++w) {
                    n2a += s_sq[rr - 1][w];
                    n2b += s_sq[rr][w];
                    d8  += s_dp[rr][w];
                }
                float na = fmaxf(sqrtf(n2a), 1e-12f);
                float nb = fmaxf(sqrtf(n2b), 1e-12f);
                acc += (double)(d8 / (na * nb));
            }
        }
#pragma unroll
        for (int o = 16; o > 0; o >>= 1)
            acc += __shfl_xor_sync(0xffffffffu, acc, o);
        if (lane == 0) g_partials[blockIdx.x] = (float)acc;
    }

    // ---- last-block-done: deterministic final reduction ----
    __threadfence();
    if (tid == 0) {
        unsigned int prev_cnt = atomicAdd(&g_count, 1u);
        s_last = (prev_cnt == gridDim.x - 1);
    }
    __syncthreads();

    if (s_last) {
        double* sd = reinterpret_cast<double*>(&s_sq[0][0]);  // dead storage reuse
        const int nb = gridDim.x;
        double a = 0.0;
        for (int i = tid; i < nb; i += NTHREADS)
            a += (double)__ldcg(&g_partials[i]);
        sd[tid] = a;
        __syncthreads();
#pragma unroll
        for (int o = NTHREADS / 2; o > 0; o >>= 1) {
            if (tid < o) sd[tid] += sd[tid + o];
            __syncthreads();
        }
        if (tid == 0) {
            out[0] = (float)(-2.0 * 0.01 * sd[0] / (double)(N - 1));
            g_count = 0;  // reset for next graph replay
        }
    }
}

extern "C" void kernel_launch(void* const* d_in, const int* in_sizes, int n_in,
                              void* d_out, int out_size) {
    const float* x = (const float*)d_in[0];
    const int N = in_sizes[0] / COLS;            // 65536
    const int nblocks = (N - 1 + RPB - 1) / RPB; // 1024
    pair_dot_fused_kernel<<<nblocks, NTHREADS>>>(x, N, (float*)d_out);
}

// round 8
// speedup vs baseline: 1.0725x; 1.0340x over previous
#include <cuda_runtime.h>

// Temporal cosine regularizer, single fused kernel (R8 = R2 champion + __ldcg).
//   out = -0.02/(N-1) * sum_i <x_i,x_{i+1}> / (max(||x_i||,eps)*max(||x_{i+1}||,eps))
//
// HBM-bound, 512 MiB read-once. R2 (register pipeline, plain __ldg, occ 83%,
// 6069 GB/s) remains the fastest wall time; all cp.async smem-ring variants
// (R4-R7) were slower. R8 changes ONE thing vs R2: loads use __ldcg (L2-only,
// LDG.E.CG) since the stream has zero L1 reuse — removes L1 fill/tag overhead
// and L1tex queue pressure (L1 was 42-47% busy for nothing).

#define COLS     2048
#define RPB      64
#define NTHREADS 256

__device__ float        g_partials[8192];
__device__ unsigned int g_count = 0;

__device__ __forceinline__ float warp_reduce_f(float v) {
#pragma unroll
    for (int o = 16; o > 0; o >>= 1) v += __shfl_xor_sync(0xffffffffu, v, o);
    return v;
}

__global__ void __launch_bounds__(NTHREADS)
pair_dot_fused_kernel(const float* __restrict__ x, int N, float* __restrict__ out) {
    __shared__ float s_sq[RPB + 1][8];
    __shared__ float s_dp[RPB + 1][8];
    __shared__ bool  s_last;

    const int tid  = threadIdx.x;
    const int lane = tid & 31;
    const int warp = tid >> 5;
    const int r0   = blockIdx.x * RPB;

    // Row r0: norm^2 only; becomes "prev".
    float prev[8];
    {
        const float4* rp = reinterpret_cast<const float4*>(x + (size_t)r0 * COLS);
        float4 a = __ldcg(rp + tid);
        float4 b = __ldcg(rp + tid + NTHREADS);
        prev[0] = a.x; prev[1] = a.y; prev[2] = a.z; prev[3] = a.w;
        prev[4] = b.x; prev[5] = b.y; prev[6] = b.z; prev[7] = b.w;
        float sq = 0.0f;
#pragma unroll
        for (int j = 0; j < 8; ++j) sq = fmaf(prev[j], prev[j], sq);
        sq = warp_reduce_f(sq);
        if (lane == 0) s_sq[0][warp] = sq;
    }

    // Rows r0+1 .. r0+RPB: norm^2 and dot with previous row.
#pragma unroll 4
    for (int rr = 1; rr <= RPB; ++rr) {
        const int r = r0 + rr;
        float sq = 0.0f, dp = 0.0f;
        if (r < N) {
            const float4* rp = reinterpret_cast<const float4*>(x + (size_t)r * COLS);
            float4 a = __ldcg(rp + tid);
            float4 b = __ldcg(rp + tid + NTHREADS);
            float cur[8] = {a.x, a.y, a.z, a.w, b.x, b.y, b.z, b.w};
#pragma unroll
            for (int j = 0; j < 8; ++j) {
                sq = fmaf(cur[j], cur[j], sq);
                dp = fmaf(cur[j], prev[j], dp);
                prev[j] = cur[j];
            }
        }
        sq = warp_reduce_f(sq);
        dp = warp_reduce_f(dp);
        if (lane == 0) { s_sq[rr][warp] = sq; s_dp[rr][warp] = dp; }
    }
    __syncthreads();

    // Warp 0: combine 8 warp-partials per row, cosine terms, fp64 accumulate.
    if (warp == 0) {
        double acc = 0.0;
        for (int rr = 1 + lane; rr <= RPB; rr += 32) {
            if (r0 + rr < N) {  // dot index r0+rr-1 must be <= N-2
                float n2a = 0.0f, n2b = 0.0f, d8 = 0.0f;
#pragma unroll
                for (int w = 0; w < 8; ++w) {
                    n2a += s_sq[rr - 1][w];
                    n2b += s_sq[rr][w];
                    d8  += s_dp[rr][w];
                }
                float na = fmaxf(sqrtf(n2a), 1e-12f);
                float nb = fmaxf(sqrtf(n2b), 1e-12f);
                acc += (double)(d8 / (na * nb));
            }
        }
#pragma unroll
        for (int o = 16; o > 0; o >>= 1)
            acc += __shfl_xor_sync(0xffffffffu, acc, o);
        if (lane == 0) g_partials[blockIdx.x] = (float)acc;
    }

    // ---- last-block-done: deterministic final reduction ----
    __threadfence();
    if (tid == 0) {
        unsigned int prev_cnt = atomicAdd(&g_count, 1u);
        s_last = (prev_cnt == gridDim.x - 1);
    }
    __syncthreads();

    if (s_last) {
        __shared__ double sd[NTHREADS];
        const int nb = gridDim.x;
        double a = 0.0;
        for (int i = tid; i < nb; i += NTHREADS)
            a += (double)__ldcg(&g_partials[i]);
        sd[tid] = a;
        __syncthreads();
#pragma unroll
        for (int o = NTHREADS / 2; o > 0; o >>= 1) {
            if (tid < o) sd[tid] += sd[tid + o];
            __syncthreads();
        }
        if (tid == 0) {
            out[0] = (float)(-2.0 * 0.01 * sd[0] / (double)(N - 1));
            g_count = 0;  // reset for next graph replay
        }
    }
}

extern "C" void kernel_launch(void* const* d_in, const int* in_sizes, int n_in,
                              void* d_out, int out_size) {
    const float* x = (const float*)d_in[0];
    const int N = in_sizes[0] / COLS;            // 65536
    const int nblocks = (N - 1 + RPB - 1) / RPB; // 1024
    pair_dot_fused_kernel<<<nblocks, NTHREADS>>>(x, N, (float*)d_out);
}